// round 15
// baseline (speedup 1.0000x reference)
#include <cuda_runtime.h>
#include <cuda_bf16.h>
#include <math.h>

#define BATCH 256
#define H     128
#define NL    4
#define V     32000
#define TSTEP 32
#define NB    128
#define NT    1024
#define NUNIT 250          // v-tiles of 128, M=256 each

typedef unsigned long long ull;

// ---------------- device scratch ----------------
__device__ __align__(16) float g_h[2][NL][BATCH][H];
__device__ __align__(16) float g_c[2][NL][BATCH][H];
__device__ __align__(16) __nv_bfloat16 g_ehi[BATCH * H];
__device__ __align__(16) __nv_bfloat16 g_elo[BATCH * H];
__device__ __align__(16) __nv_bfloat16 g_Whi[V * H];
__device__ __align__(16) __nv_bfloat16 g_Wlo2[V * H];
__device__ __align__(16) float g_scr[BATCH][V];      // logits then exp, L2-resident
__device__ ull g_amax[2][BATCH];                     // packed (max,argmax) keys per parity
__device__ int g_prev[BATCH];
__device__ unsigned g_mw2key, g_mbkey;               // ordered-float atomic max keys
__device__ float g_embB;                             // sum_e (L1 bound_e)^2
__device__ int c_init, c_emb, c_log, c_done;
__device__ int c_hq[NL][4][32];                      // per-quarter LSTM layer counters
__device__ int c_redq[4][32];                        // per-quarter feedback counters

// ---------------- packed f32x2 helpers (LSTM) ----------------
__device__ __forceinline__ ull pk2(float x) {
    ull r; asm("mov.b64 %0, {%1, %1};" : "=l"(r) : "f"(x)); return r;
}
__device__ __forceinline__ ull pkc(float a, float b) {
    ull r; asm("mov.b64 %0, {%1, %2};" : "=l"(r) : "f"(a), "f"(b)); return r;
}
__device__ __forceinline__ void fma2(ull &acc, ull a, ull b) {
    asm("fma.rn.f32x2 %0, %1, %2, %3;" : "=l"(acc) : "l"(a), "l"(b), "l"(acc));
}
__device__ __forceinline__ float2 upk(ull v) {
    float2 r; asm("mov.b64 {%0, %1}, %2;" : "=f"(r.x), "=f"(r.y) : "l"(v)); return r;
}
__device__ __forceinline__ float sigm(float x) { return 1.0f / (1.0f + expf(-x)); }

// ordered-float <-> uint (monotone)
__device__ __forceinline__ unsigned ordk(float f) {
    unsigned u = __float_as_uint(f);
    return (u & 0x80000000u) ? ~u : (u | 0x80000000u);
}
__device__ __forceinline__ ull mkkey(float o, int v) {
    return ((ull)ordk(o) << 32) | (ull)(0xffffffffu - (unsigned)v);
}
__device__ __forceinline__ float keyf(unsigned k) {
    return __uint_as_float((k & 0x80000000u) ? (k & 0x7fffffffu) : ~k);
}

// ---------------- dataflow sync ----------------
__device__ __forceinline__ void waitcnt(int* c, int target) {
    if (threadIdx.x == 0) {
        volatile int* vc = (volatile int*)c;
        while (*vc < target) __nanosleep(64);
        __threadfence();
    }
    __syncthreads();
}
__device__ __forceinline__ void bumpcnt(int* c) {
    __syncthreads();
    if (threadIdx.x == 0) { __threadfence(); atomicAdd(c, 1); }
}

// ---------------- mma.sync / ldmatrix ----------------
__device__ __forceinline__ void ldmx4(unsigned &r0, unsigned &r1, unsigned &r2,
                                      unsigned &r3, unsigned addr) {
    asm volatile("ldmatrix.sync.aligned.m8n8.x4.shared.b16 {%0,%1,%2,%3}, [%4];"
                 : "=r"(r0), "=r"(r1), "=r"(r2), "=r"(r3) : "r"(addr));
}
__device__ __forceinline__ void mma_bf16(float* c, const unsigned* a, const unsigned* b) {
    asm volatile("mma.sync.aligned.m16n8k16.row.col.f32.bf16.bf16.f32 "
                 "{%0,%1,%2,%3}, {%4,%5,%6,%7}, {%8,%9}, {%0,%1,%2,%3};"
                 : "+f"(c[0]), "+f"(c[1]), "+f"(c[2]), "+f"(c[3])
                 : "r"(a[0]), "r"(a[1]), "r"(a[2]), "r"(a[3]), "r"(b[0]), "r"(b[1]));
}

// smem layout (bytes)
#define SA_HI  1024
#define SA_LO  (SA_HI + 69632)
#define SB_HI  (SA_LO + 69632)
#define SB_LO  (SB_HI + 34816)
#define SM_KEY (SB_LO + 34816)
#define SM_PRT (SM_KEY + 8192)          // deferred partial sums [2][8]
#define SMEM_BYTES (SM_PRT + 4096)      // 222208
#define DLO_A  69632
#define DLO_B  34816

// ============================================================================
__global__ void __launch_bounds__(NT, 1)
decoder_kernel(const float* __restrict__ hidden, const float* __restrict__ cell,
               const float* __restrict__ W_in,  const float* __restrict__ b_in,
               const float* __restrict__ W_ih,  const float* __restrict__ W_hh,
               const float* __restrict__ b_ih,  const float* __restrict__ b_hh,
               const float* __restrict__ W_re,  const float* __restrict__ b_re,
               const float* __restrict__ W_lo,  const float* __restrict__ b_lo,
               const int*   __restrict__ eos,
               float* __restrict__ out)
{
    extern __shared__ char smraw[];
    unsigned smem_base;
    asm("{ .reg .u64 t; cvta.to.shared.u64 t, %1; cvt.u32.u64 %0, t; }"
        : "=r"(smem_base) : "l"(smraw));
    const int tid = threadIdx.x;
    const int bid = blockIdx.x;

    // ---- init: state copy + W_lo row-wise split + norm bounds ----
    {
        int j = bid * NT + tid;                 // NL*BATCH*H = 131072
        __stcg(&(&g_h[0][0][0][0])[j], hidden[j]);
        __stcg(&(&g_c[0][0][0][0])[j], cell[j]);
        if (bid == 0 && tid < BATCH) __stcg(&g_prev[tid], __ldg(&eos[0]));
        if (bid == 0 && tid < 2 * BATCH) ((ull*)g_amax)[tid] = 0ull;

        int v = bid * NT + tid;                 // one row per thread (v < 32000)
        if (v < V) {
            const float4* wr = (const float4*)(W_lo + (size_t)v * H);
            uint4* oh = (uint4*)(g_Whi  + (size_t)v * H);
            uint4* ol = (uint4*)(g_Wlo2 + (size_t)v * H);
            float nrm = 0.f;
#pragma unroll 4
            for (int jq = 0; jq < 16; jq++) {
                float4 a = __ldg(&wr[2 * jq]);
                float4 b2 = __ldg(&wr[2 * jq + 1]);
                float w8[8] = {a.x, a.y, a.z, a.w, b2.x, b2.y, b2.z, b2.w};
                unsigned hh[4], llp[4];
#pragma unroll
                for (int p = 0; p < 4; p++) {
                    __nv_bfloat16 h0 = __float2bfloat16(w8[2 * p]);
                    __nv_bfloat16 h1 = __float2bfloat16(w8[2 * p + 1]);
                    __nv_bfloat16 l0 = __float2bfloat16(w8[2 * p] - __bfloat162float(h0));
                    __nv_bfloat16 l1 = __float2bfloat16(w8[2 * p + 1] - __bfloat162float(h1));
                    hh[p]  = (unsigned)__bfloat16_as_ushort(h0) | ((unsigned)__bfloat16_as_ushort(h1) << 16);
                    llp[p] = (unsigned)__bfloat16_as_ushort(l0) | ((unsigned)__bfloat16_as_ushort(l1) << 16);
                    nrm += w8[2 * p] * w8[2 * p] + w8[2 * p + 1] * w8[2 * p + 1];
                }
                oh[jq] = make_uint4(hh[0], hh[1], hh[2], hh[3]);
                ol[jq] = make_uint4(llp[0], llp[1], llp[2], llp[3]);
            }
            atomicMax(&g_mw2key, ordk(nrm));
            atomicMax(&g_mbkey, ordk(fabsf(__ldg(&b_lo[v]))));
        }
        if (bid == 0) {                         // emb L1 bound (block 0)
            float* tmp = (float*)(smraw + SA_HI);
            if (tid < 128) {
                float s1 = 0.f;
                for (int k = 0; k < H; k++) s1 += fabsf(__ldg(&W_re[tid * H + k]));
                s1 += fabsf(__ldg(&b_re[tid]));
                tmp[tid] = s1 * s1;
            }
            __syncthreads();
            if (tid == 0) {
                float s = 0.f;
                for (int e = 0; e < 128; e++) s += tmp[e];
                g_embB = s;
            }
        }
    }
    bumpcnt(&c_init);
    waitcnt(&c_init, NB);

    const float Mhat = sqrtf(__ldcg(&g_embB)) * sqrtf(keyf(*(volatile unsigned*)&g_mw2key))
                     + keyf(*(volatile unsigned*)&g_mbkey);

    const int ut = bid & 31, q = bid >> 5;
    const int u0 = ut * 4, b0 = q * 64;        // LSTM slice: 4 units x 64 rows

    // deferred-softmax state (threads >= 512): full softmax off critical path
    float4* nzRow = 0;                         // g_scr row (logits -> exp in place)
    float4* nzOut = 0;
    float nzPS = 0.f, nzInv = 0.f;
    int nzValid = 0;

    for (int t = 0; t < TSTEP; t++) {
        const int rp = t & 1, wp = rp ^ 1;

        // ================= LSTM: 4 layers (per-quarter sync) =================
        for (int l = 0; l < NL; l++) {
            if (l == 0) waitcnt(&c_redq[q][0], 32 * t);
            else        waitcnt(&c_hq[l - 1][q][0], 32 * (t + 1));

            ull*   ws = (ull*)(smraw + 1024);      // [8][258]
            float* xs = (float*)(ws + 8 * 258);    // [64][132]
            float* hs = xs + 64 * 132;             // [64][132]

            for (int j = tid; j < 8 * 256; j += NT) {
                int ci = j >> 8, k = j & 255;
                int ul = ci >> 1, ch = ci & 1;
                int g0 = (ch ? 256 : 0) + u0 + ul;
                const float* Ws = ((k < 128) ? W_ih : W_hh) + l * 512 * H;
                int kk = k & 127;
                ws[ci * 258 + k] = pkc(__ldg(&Ws[g0 * H + kk]), __ldg(&Ws[(g0 + 128) * H + kk]));
            }
            if (l == 0) {
                for (int j = tid; j < 64 * H; j += NT) {
                    int bl = j >> 7, k = j & 127;
                    int tok = __ldcg(&g_prev[b0 + bl]);
                    xs[bl * 132 + k] = __ldg(&W_in[tok * H + k]) + __ldg(&b_in[k]);
                }
            } else {
                for (int j = tid; j < 64 * H; j += NT) {
                    int bl = j >> 7, k = j & 127;
                    xs[bl * 132 + k] = __ldcg(&g_h[wp][l - 1][b0 + bl][k]);
                }
            }
            for (int j = tid; j < 64 * H; j += NT) {
                int bl = j >> 7, k = j & 127;
                hs[bl * 132 + k] = __ldcg(&g_h[rp][l][b0 + bl][k]);
            }
            __syncthreads();

            if (tid < 512) {
                int bl = tid >> 3, ul = (tid >> 1) & 3, ch = tid & 1;
                const ull*   w  = ws + (ul * 2 + ch) * 258;
                const float* xv = xs + bl * 132;
                const float* hv = hs + bl * 132;
                ull acc = 0ull;
#pragma unroll 8
                for (int k = 0; k < 128; k += 2) {
                    float2 x2 = *(const float2*)(xv + k);
                    ulonglong2 w2 = *(const ulonglong2*)(w + k);
                    fma2(acc, pk2(x2.x), w2.x);
                    fma2(acc, pk2(x2.y), w2.y);
                }
#pragma unroll 8
                for (int k = 0; k < 128; k += 2) {
                    float2 h2 = *(const float2*)(hv + k);
                    ulonglong2 w2 = *(const ulonglong2*)(w + 128 + k);
                    fma2(acc, pk2(h2.x), w2.x);
                    fma2(acc, pk2(h2.y), w2.y);
                }
                float2 vv = upk(acc);
                int u = u0 + ul, b = b0 + bl;
                int gA = (ch ? 256 : 0) + u;
                float a0 = vv.x + __ldg(&b_ih[l * 512 + gA])       + __ldg(&b_hh[l * 512 + gA]);
                float a1 = vv.y + __ldg(&b_ih[l * 512 + gA + 128]) + __ldg(&b_hh[l * 512 + gA + 128]);
                float p0 = __shfl_xor_sync(0xffffffffu, a0, 1);
                float p1 = __shfl_xor_sync(0xffffffffu, a1, 1);
                if (ch == 0) {
                    float co = __ldcg(&g_c[rp][l][b][u]);
                    float cn = sigm(a1) * co + sigm(a0) * tanhf(p0);
                    float hn = sigm(p1) * tanhf(cn);
                    __stcg(&g_c[wp][l][b][u], cn);
                    __stcg(&g_h[wp][l][b][u], hn);
                }
            } else if (nzValid) {
                int lane8 = tid & 255;
                if (l < 3) {                       // pass1 third: exp + partial sum
                    int lo = (l == 0) ? 0 : (l == 1) ? 2667 : 5334;
                    int hi = (l == 0) ? 2667 : (l == 1) ? 5334 : 8000;
                    for (int i = lo + lane8; i < hi; i += 256) {
                        float4 o4 = __ldcg(nzRow + i);
                        float4 e4 = { __expf(o4.x - Mhat), __expf(o4.y - Mhat),
                                      __expf(o4.z - Mhat), __expf(o4.w - Mhat) };
                        __stcg(nzRow + i, e4);
                        nzPS += (e4.x + e4.y) + (e4.z + e4.w);
                    }
                    if (l == 2) {                  // warp-reduce, publish partials
                        float s = nzPS;
#pragma unroll
                        for (int off = 16; off; off >>= 1)
                            s += __shfl_xor_sync(0xffffffffu, s, off);
                        if ((tid & 31) == 0) {
                            int half = (tid >> 8) & 1, wr8 = (tid & 255) >> 5;
                            ((float*)(smraw + SM_PRT))[half * 8 + wr8] = s;
                        }
                    }
                } else {                           // l==3: inv + pass2 first half
                    const float* part = (const float*)(smraw + SM_PRT) + ((tid >> 8) & 1) * 8;
                    float s = ((part[0] + part[1]) + (part[2] + part[3]))
                            + ((part[4] + part[5]) + (part[6] + part[7]));
                    nzInv = 1.f / s;
                    for (int i = lane8; i < 4000; i += 256) {
                        float4 e = __ldcg(nzRow + i);
                        float4 o = { e.x * nzInv, e.y * nzInv, e.z * nzInv, e.w * nzInv };
                        __stcs(nzOut + i, o);
                    }
                }
            }
            bumpcnt(&c_hq[l][q][0]);
        }

        // ================= emb: fp32 + bf16 hi/lo split ======================
        {
            waitcnt(&c_hq[NL - 1][q][0], 32 * (t + 1));
            float* hsm = (float*)(smraw + 1024);   // [64][132]
            float* Wts = hsm + 64 * 132;           // [4][128]
            int r0 = q * 64, e0 = ut * 4;
            for (int j = tid; j < 64 * H; j += NT) {
                int row = j >> 7, k = j & 127;
                hsm[row * 132 + k] = __ldcg(&g_h[wp][NL - 1][r0 + row][k]);
            }
            for (int j = tid; j < 4 * H; j += NT)
                Wts[j] = __ldg(&W_re[(e0 + (j >> 7)) * H + (j & 127)]);
            __syncthreads();
            if (tid < 256) {
                int row = tid & 63, e = tid >> 6;
                const float* hv = hsm + row * 132;
                const float* wv = Wts + e * 128;
                float acc = 0.f;
#pragma unroll 8
                for (int k = 0; k < 128; k += 4) {
                    float4 h4 = *(const float4*)(hv + k);
                    float4 w4 = *(const float4*)(wv + k);
                    acc = fmaf(h4.x, w4.x, acc); acc = fmaf(h4.y, w4.y, acc);
                    acc = fmaf(h4.z, w4.z, acc); acc = fmaf(h4.w, w4.w, acc);
                }
                float ev = acc + __ldg(&b_re[e0 + e]);
                __nv_bfloat16 hi = __float2bfloat16(ev);
                int idx = (r0 + row) * H + e0 + e;
                g_ehi[idx] = hi;
                g_elo[idx] = __float2bfloat16(ev - __bfloat162float(hi));
            } else if (tid >= 512 && nzValid) {    // pass2 second half
                for (int i = 4000 + (tid & 255); i < 8000; i += 256) {
                    float4 e = __ldcg(nzRow + i);
                    float4 o = { e.x * nzInv, e.y * nzInv, e.z * nzInv, e.w * nzInv };
                    __stcs(nzOut + i, o);
                }
            }
            bumpcnt(&c_emb);
        }

        // ================= logits: split-bf16 mma.sync, raw-o epilogue =======
        waitcnt(&c_emb, NB * (t + 1));     // also guarantees all softmax(t-1) done
        {
            {   // stage A (emb hi/lo)
                const uint4* eh = (const uint4*)g_ehi;
                const uint4* el = (const uint4*)g_elo;
                for (int j = tid; j < 4096; j += NT) {
                    int r = j >> 4, kq = j & 15;
                    *(uint4*)(smraw + SA_HI + r * 272 + kq * 16) = __ldcg(&eh[j]);
                    *(uint4*)(smraw + SA_LO + r * 272 + kq * 16) = __ldcg(&el[j]);
                }
            }
            const int lane = tid & 31, wid = tid >> 5;
            const int m_base = (wid >> 2) * 32;
            const int n_base = (wid & 3) * 32;
            const int arow  = lane & 15;
            const int ahoff = ((lane >> 4) & 1) * 16;
            const int nrow  = (lane & 7) + ((lane & 16) >> 1);
            const int bhoff = ((lane >> 3) & 1) * 16;
            const int qrow = lane >> 2, qcol = (lane & 3) * 2;
            ull* keys = (ull*)(smraw + SM_KEY);    // [256][4]
            ull gbest = 0ull;

            for (int u = bid; u < NUNIT; u += NB) {
                int v0 = u * 128;
                {
                    const uint4* wh = (const uint4*)g_Whi;
                    const uint4* wl = (const uint4*)g_Wlo2;
                    int sb = v0 * 16;
                    for (int j = tid; j < 2048; j += NT) {
                        int r = j >> 4, kq = j & 15;
                        *(uint4*)(smraw + SB_HI + r * 272 + kq * 16) = __ldg(&wh[sb + j]);
                        *(uint4*)(smraw + SB_LO + r * 272 + kq * 16) = __ldg(&wl[sb + j]);
                    }
                }
                __syncthreads();

                float c[2][4][4];
#pragma unroll
                for (int mi = 0; mi < 2; mi++)
#pragma unroll
                    for (int n8 = 0; n8 < 4; n8++)
#pragma unroll
                        for (int e = 0; e < 4; e++) c[mi][n8][e] = 0.f;

                unsigned aB = smem_base + SA_HI + (unsigned)(m_base + arow) * 272 + ahoff;
                unsigned bB = smem_base + SB_HI + (unsigned)(n_base + nrow) * 272 + bhoff;
#pragma unroll 1
                for (int ks = 0; ks < 8; ks++) {
                    unsigned koff = ks * 32;
                    unsigned ah[2][4], al[2][4], bb[4][2];
                    ldmx4(ah[0][0], ah[0][1], ah[0][2], ah[0][3], aB + koff);
                    ldmx4(ah[1][0], ah[1][1], ah[1][2], ah[1][3], aB + 16 * 272 + koff);
                    ldmx4(bb[0][0], bb[0][1], bb[1][0], bb[1][1], bB + koff);
                    ldmx4(bb[2][0], bb[2][1], bb[3][0], bb[3][1], bB + 16 * 272 + koff);
#pragma unroll
                    for (int mi = 0; mi < 2; mi++)
#pragma unroll
                        for (int n8 = 0; n8 < 4; n8++)
                            mma_bf16(c[mi][n8], ah[mi], bb[n8]);
                    ldmx4(al[0][0], al[0][1], al[0][2], al[0][3], aB + DLO_A + koff);
                    ldmx4(al[1][0], al[1][1], al[1][2], al[1][3], aB + DLO_A + 16 * 272 + koff);
#pragma unroll
                    for (int mi = 0; mi < 2; mi++)
#pragma unroll
                        for (int n8 = 0; n8 < 4; n8++)
                            mma_bf16(c[mi][n8], al[mi], bb[n8]);
                    ldmx4(bb[0][0], bb[0][1], bb[1][0], bb[1][1], bB + DLO_B + koff);
                    ldmx4(bb[2][0], bb[2][1], bb[3][0], bb[3][1], bB + DLO_B + 16 * 272 + koff);
#pragma unroll
                    for (int mi = 0; mi < 2; mi++)
#pragma unroll
                        for (int n8 = 0; n8 < 4; n8++)
                            mma_bf16(c[mi][n8], ah[mi], bb[n8]);
                }

                // epilogue: bias, argmax keys, store RAW logits (no exp!)
                ull bk[2][2] = {{0ull, 0ull}, {0ull, 0ull}};
#pragma unroll
                for (int mi = 0; mi < 2; mi++) {
                    int r = m_base + mi * 16 + qrow;
#pragma unroll
                    for (int n8 = 0; n8 < 4; n8++) {
                        int v = v0 + n_base + n8 * 8 + qcol;
                        float2 bl = *(const float2*)(b_lo + v);
                        float o0 = c[mi][n8][0] + bl.x, o1 = c[mi][n8][1] + bl.y;
                        float o2 = c[mi][n8][2] + bl.x, o3 = c[mi][n8][3] + bl.y;
                        bk[mi][0] = max(bk[mi][0], max(mkkey(o0, v), mkkey(o1, v + 1)));
                        bk[mi][1] = max(bk[mi][1], max(mkkey(o2, v), mkkey(o3, v + 1)));
                        float2 w0 = { o0, o1 }, w1 = { o2, o3 };
                        __stcg((float2*)&g_scr[r][v],     w0);
                        __stcg((float2*)&g_scr[r + 8][v], w1);
                    }
                }
#pragma unroll
                for (int mi = 0; mi < 2; mi++)
#pragma unroll
                    for (int hh = 0; hh < 2; hh++) {
                        ull k = bk[mi][hh];
                        k = max(k, __shfl_xor_sync(0xffffffffu, k, 1));
                        k = max(k, __shfl_xor_sync(0xffffffffu, k, 2));
                        bk[mi][hh] = k;
                    }
                if ((lane & 3) == 0) {
                    int nw = wid & 3;
#pragma unroll
                    for (int mi = 0; mi < 2; mi++)
#pragma unroll
                        for (int hh = 0; hh < 2; hh++)
                            keys[(m_base + mi * 16 + qrow + hh * 8) * 4 + nw] = bk[mi][hh];
                }
                __syncthreads();
                if (tid < 256)
                    gbest = max(gbest, max(max(keys[tid * 4], keys[tid * 4 + 1]),
                                           max(keys[tid * 4 + 2], keys[tid * 4 + 3])));
            }
            if (tid < 256 && gbest != 0ull)
                atomicMax(&g_amax[rp][tid], gbest);
        }
        bumpcnt(&c_log);

        // ====== head: argmax feedback only; softmax fully deferred ===========
        waitcnt(&c_log, NB * (t + 1));
        if (t < TSTEP - 1) {
            if ((tid & 511) == 0) {                // tid 0 and 512: one per row
                int half = tid >> 9;
                int r = 2 * bid + half;
                ull key = *(volatile ull*)&g_amax[rp][r];
                __stcg(&g_prev[r], (int)(0xffffffffu - (unsigned)(key & 0xffffffffu)));
                atomicExch(&g_amax[rp][r], 0ull);
            }
            if (tid >= 512) {                      // arm deferred softmax
                int rn = 2 * bid + ((tid >> 8) & 1);
                nzRow = (float4*)&g_scr[rn][0];
                nzOut = (float4*)(out + ((size_t)t * BATCH + rn) * V);
                nzPS = 0.f; nzValid = 1;
            }
            bumpcnt(&c_redq[bid >> 5][0]);         // release step t+1 LSTM now
        } else {                                   // t=31: inline 2-pass softmax
            bumpcnt(&c_redq[bid >> 5][0]);
            float* sred = (float*)(smraw + 1024);  // [32]
            float* sInv = sred + 32;               // [2]
            int half = tid >> 9, lane9 = tid & 511;
            int r = 2 * bid + half;
            if (lane9 == 0) atomicExch(&g_amax[rp][r], 0ull);
            float4* row4 = (float4*)&g_scr[r][0];
            float s = 0.f;
            for (int i = lane9; i < 8000; i += 512) {
                float4 o4 = __ldcg(row4 + i);
                float4 e4 = { __expf(o4.x - Mhat), __expf(o4.y - Mhat),
                              __expf(o4.z - Mhat), __expf(o4.w - Mhat) };
                __stcg(row4 + i, e4);
                s += (e4.x + e4.y) + (e4.z + e4.w);
            }
#pragma unroll
            for (int off = 16; off; off >>= 1)
                s += __shfl_xor_sync(0xffffffffu, s, off);
            if ((tid & 31) == 0) sred[tid >> 5] = s;
            __syncthreads();
            if (lane9 == 0) {
                float tot = 0.f;
                for (int w = 0; w < 16; w++) tot += sred[half * 16 + w];
                sInv[half] = 1.f / tot;
            }
            __syncthreads();
            float invv = sInv[half];
            float4* orow = (float4*)(out + ((size_t)t * BATCH + r) * V);
            for (int i = lane9; i < 8000; i += 512) {
                float4 e = __ldcg(row4 + i);
                float4 o = { e.x * invv, e.y * invv, e.z * invv, e.w * invv };
                __stcs(orow + i, o);
            }
        }
    }

    // ---- reset counters for graph replay ----
    __syncthreads();
    if (tid == 0) {
        __threadfence();
        atomicAdd(&c_done, 1);
        if (bid == 0) {
            volatile int* vd = (volatile int*)&c_done;
            while (*vd < NB) __nanosleep(64);
            c_init = 0; c_emb = 0; c_log = 0;
            g_mw2key = 0; g_mbkey = 0;
            for (int l = 0; l < NL; l++)
                for (int qq = 0; qq < 4; qq++) c_hq[l][qq][0] = 0;
            for (int qq = 0; qq < 4; qq++) c_redq[qq][0] = 0;
            __threadfence();
            *(volatile int*)&c_done = 0;
        }
    }
}

// ---------------- launch ----------------
extern "C" void kernel_launch(void* const* d_in, const int* in_sizes, int n_in,
                              void* d_out, int out_size) {
    const float* hidden = (const float*)d_in[0];
    const float* cell   = (const float*)d_in[1];
    const float* W_in   = (const float*)d_in[2];
    const float* b_in   = (const float*)d_in[3];
    const float* W_ih   = (const float*)d_in[4];
    const float* W_hh   = (const float*)d_in[5];
    const float* b_ih   = (const float*)d_in[6];
    const float* b_hh   = (const float*)d_in[7];
    const float* W_re   = (const float*)d_in[8];
    const float* b_re   = (const float*)d_in[9];
    const float* W_lo   = (const float*)d_in[10];
    const float* b_lo   = (const float*)d_in[11];
    const int*   eos    = (const int*)d_in[12];
    float* out = (float*)d_out;

    cudaFuncSetAttribute(decoder_kernel, cudaFuncAttributeMaxDynamicSharedMemorySize, SMEM_BYTES);
    decoder_kernel<<<NB, NT, SMEM_BYTES>>>(hidden, cell, W_in, b_in, W_ih, W_hh,
                                           b_ih, b_hh, W_re, b_re, W_lo, b_lo, eos, out);
}

// round 16
// speedup vs baseline: 1.1001x; 1.1001x over previous
#include <cuda_runtime.h>
#include <cuda_bf16.h>
#include <math.h>

#define BATCH 256
#define H     128
#define NL    4
#define V     32000
#define TSTEP 32
#define NB    128
#define NT    1024
#define NUNIT 250          // v-tiles of 128, M=256 each

typedef unsigned long long ull;

// ---------------- device scratch ----------------
__device__ __align__(16) float g_h[2][NL][BATCH][H];
__device__ __align__(16) float g_c[2][NL][BATCH][H];
__device__ __align__(16) __nv_bfloat16 g_ehi[BATCH * H];
__device__ __align__(16) __nv_bfloat16 g_elo[BATCH * H];
__device__ __align__(16) __nv_bfloat16 g_Whi[V * H];
__device__ __align__(16) __nv_bfloat16 g_Wlo2[V * H];
__device__ __align__(16) float g_blo[V];             // b_lo - Mhat (shifted bias)
__device__ __align__(16) float g_scr[BATCH][V];      // exp values, L2-resident
__device__ __align__(16) float g_psum[BATCH][NB];    // per-block row partial sums
__device__ ull g_amax[2][BATCH];                     // packed (max,argmax) keys per parity
__device__ int g_prev[BATCH];
__device__ unsigned g_mw2key, g_mbkey;               // ordered-float atomic max keys
__device__ float g_embB;                             // sum_e (L1 bound_e)^2
__device__ int c_init, c_emb, c_log, c_done;
__device__ int c_hq[NL][4][32];                      // per-quarter LSTM layer counters
__device__ int c_redq[4][32];                        // per-quarter feedback counters

// ---------------- packed f32x2 helpers (LSTM) ----------------
__device__ __forceinline__ ull pk2(float x) {
    ull r; asm("mov.b64 %0, {%1, %1};" : "=l"(r) : "f"(x)); return r;
}
__device__ __forceinline__ ull pkc(float a, float b) {
    ull r; asm("mov.b64 %0, {%1, %2};" : "=l"(r) : "f"(a), "f"(b)); return r;
}
__device__ __forceinline__ void fma2(ull &acc, ull a, ull b) {
    asm("fma.rn.f32x2 %0, %1, %2, %3;" : "=l"(acc) : "l"(a), "l"(b), "l"(acc));
}
__device__ __forceinline__ float2 upk(ull v) {
    float2 r; asm("mov.b64 {%0, %1}, %2;" : "=f"(r.x), "=f"(r.y) : "l"(v)); return r;
}
__device__ __forceinline__ float sigm(float x) { return 1.0f / (1.0f + expf(-x)); }

// ordered-float <-> uint (monotone)
__device__ __forceinline__ unsigned ordk(float f) {
    unsigned u = __float_as_uint(f);
    return (u & 0x80000000u) ? ~u : (u | 0x80000000u);
}
__device__ __forceinline__ ull mkkey(float o, int v) {
    return ((ull)ordk(o) << 32) | (ull)(0xffffffffu - (unsigned)v);
}
__device__ __forceinline__ float keyf(unsigned k) {
    return __uint_as_float((k & 0x80000000u) ? (k & 0x7fffffffu) : ~k);
}

// ---------------- dataflow sync ----------------
__device__ __forceinline__ void waitcnt(int* c, int target) {
    if (threadIdx.x == 0) {
        volatile int* vc = (volatile int*)c;
        while (*vc < target) __nanosleep(64);
        __threadfence();
    }
    __syncthreads();
}
__device__ __forceinline__ void bumpcnt(int* c) {
    __syncthreads();
    if (threadIdx.x == 0) { __threadfence(); atomicAdd(c, 1); }
}

// ---------------- mma.sync / ldmatrix ----------------
__device__ __forceinline__ void ldmx4(unsigned &r0, unsigned &r1, unsigned &r2,
                                      unsigned &r3, unsigned addr) {
    asm volatile("ldmatrix.sync.aligned.m8n8.x4.shared.b16 {%0,%1,%2,%3}, [%4];"
                 : "=r"(r0), "=r"(r1), "=r"(r2), "=r"(r3) : "r"(addr));
}
__device__ __forceinline__ void mma_bf16(float* c, const unsigned* a, const unsigned* b) {
    asm volatile("mma.sync.aligned.m16n8k16.row.col.f32.bf16.bf16.f32 "
                 "{%0,%1,%2,%3}, {%4,%5,%6,%7}, {%8,%9}, {%0,%1,%2,%3};"
                 : "+f"(c[0]), "+f"(c[1]), "+f"(c[2]), "+f"(c[3])
                 : "r"(a[0]), "r"(a[1]), "r"(a[2]), "r"(a[3]), "r"(b[0]), "r"(b[1]));
}

// smem layout (bytes)
#define SA_HI  1024
#define SA_LO  (SA_HI + 69632)
#define SB_HI  (SA_LO + 69632)
#define SB_LO  (SB_HI + 34816)
#define SM_KEY (SB_LO + 34816)
#define SM_SUM (SM_KEY + 8192)
#define SMEM_BYTES (SM_SUM + 4096)      // 222208
#define DLO_A  69632
#define DLO_B  34816

// ============================================================================
__global__ void __launch_bounds__(NT, 1)
decoder_kernel(const float* __restrict__ hidden, const float* __restrict__ cell,
               const float* __restrict__ W_in,  const float* __restrict__ b_in,
               const float* __restrict__ W_ih,  const float* __restrict__ W_hh,
               const float* __restrict__ b_ih,  const float* __restrict__ b_hh,
               const float* __restrict__ W_re,  const float* __restrict__ b_re,
               const float* __restrict__ W_lo,  const float* __restrict__ b_lo,
               const int*   __restrict__ eos,
               float* __restrict__ out)
{
    extern __shared__ char smraw[];
    unsigned smem_base;
    asm("{ .reg .u64 t; cvta.to.shared.u64 t, %1; cvt.u32.u64 %0, t; }"
        : "=r"(smem_base) : "l"(smraw));
    const int tid = threadIdx.x;
    const int bid = blockIdx.x;

    // ---- init: state copy + W_lo row-wise split + norm bounds ----
    {
        int j = bid * NT + tid;                 // NL*BATCH*H = 131072
        __stcg(&(&g_h[0][0][0][0])[j], hidden[j]);
        __stcg(&(&g_c[0][0][0][0])[j], cell[j]);
        if (bid == 0 && tid < BATCH) __stcg(&g_prev[tid], __ldg(&eos[0]));
        if (bid == 0 && tid < 2 * BATCH) ((ull*)g_amax)[tid] = 0ull;

        int v = bid * NT + tid;                 // one row per thread (v < 32000)
        if (v < V) {
            const float4* wr = (const float4*)(W_lo + (size_t)v * H);
            uint4* oh = (uint4*)(g_Whi  + (size_t)v * H);
            uint4* ol = (uint4*)(g_Wlo2 + (size_t)v * H);
            float nrm = 0.f;
#pragma unroll 4
            for (int jq = 0; jq < 16; jq++) {
                float4 a = __ldg(&wr[2 * jq]);
                float4 b2 = __ldg(&wr[2 * jq + 1]);
                float w8[8] = {a.x, a.y, a.z, a.w, b2.x, b2.y, b2.z, b2.w};
                unsigned hh[4], llp[4];
#pragma unroll
                for (int p = 0; p < 4; p++) {
                    __nv_bfloat16 h0 = __float2bfloat16(w8[2 * p]);
                    __nv_bfloat16 h1 = __float2bfloat16(w8[2 * p + 1]);
                    __nv_bfloat16 l0 = __float2bfloat16(w8[2 * p] - __bfloat162float(h0));
                    __nv_bfloat16 l1 = __float2bfloat16(w8[2 * p + 1] - __bfloat162float(h1));
                    hh[p]  = (unsigned)__bfloat16_as_ushort(h0) | ((unsigned)__bfloat16_as_ushort(h1) << 16);
                    llp[p] = (unsigned)__bfloat16_as_ushort(l0) | ((unsigned)__bfloat16_as_ushort(l1) << 16);
                    nrm += w8[2 * p] * w8[2 * p] + w8[2 * p + 1] * w8[2 * p + 1];
                }
                oh[jq] = make_uint4(hh[0], hh[1], hh[2], hh[3]);
                ol[jq] = make_uint4(llp[0], llp[1], llp[2], llp[3]);
            }
            atomicMax(&g_mw2key, ordk(nrm));
            atomicMax(&g_mbkey, ordk(fabsf(__ldg(&b_lo[v]))));
        }
        if (bid == 0) {                         // emb L1 bound (block 0)
            float* tmp = (float*)(smraw + SA_HI);
            if (tid < 128) {
                float s1 = 0.f;
                for (int k = 0; k < H; k++) s1 += fabsf(__ldg(&W_re[tid * H + k]));
                s1 += fabsf(__ldg(&b_re[tid]));
                tmp[tid] = s1 * s1;
            }
            __syncthreads();
            if (tid == 0) {
                float s = 0.f;
                for (int e = 0; e < 128; e++) s += tmp[e];
                g_embB = s;
            }
        }
    }
    bumpcnt(&c_init);
    waitcnt(&c_init, NB);

    const float Mhat = sqrtf(__ldcg(&g_embB)) * sqrtf(keyf(*(volatile unsigned*)&g_mw2key))
                     + keyf(*(volatile unsigned*)&g_mbkey);

    // shifted bias slice: visible to all epilogue readers via the c_emb>=NB wait
    if (tid < 250) {
        int v = bid * 250 + tid;
        __stcg(&g_blo[v], __ldg(&b_lo[v]) - Mhat);
    }

    const int ut = bid & 31, q = bid >> 5;
    const int u0 = ut * 4, b0 = q * 64;        // LSTM slice: 4 units x 64 rows

    // deferred-normalize state (threads >= 512)
    const float4* nzIn  = 0;
    float4*       nzOut = 0;
    float nzInv = 0.f;
    int nzValid = 0;

    for (int t = 0; t < TSTEP; t++) {
        const int rp = t & 1, wp = rp ^ 1;

        // ================= LSTM: 4 layers (per-quarter sync) =================
        for (int l = 0; l < NL; l++) {
            if (l == 0) waitcnt(&c_redq[q][0], 32 * t);
            else        waitcnt(&c_hq[l - 1][q][0], 32 * (t + 1));

            ull*   ws = (ull*)(smraw + 1024);      // [8][258]
            float* xs = (float*)(ws + 8 * 258);    // [64][132]
            float* hs = xs + 64 * 132;             // [64][132]

            for (int j = tid; j < 8 * 256; j += NT) {
                int ci = j >> 8, k = j & 255;
                int ul = ci >> 1, ch = ci & 1;
                int g0 = (ch ? 256 : 0) + u0 + ul;
                const float* Ws = ((k < 128) ? W_ih : W_hh) + l * 512 * H;
                int kk = k & 127;
                ws[ci * 258 + k] = pkc(__ldg(&Ws[g0 * H + kk]), __ldg(&Ws[(g0 + 128) * H + kk]));
            }
            if (l == 0) {
                for (int j = tid; j < 64 * H; j += NT) {
                    int bl = j >> 7, k = j & 127;
                    int tok = __ldcg(&g_prev[b0 + bl]);
                    xs[bl * 132 + k] = __ldg(&W_in[tok * H + k]) + __ldg(&b_in[k]);
                }
            } else {
                for (int j = tid; j < 64 * H; j += NT) {
                    int bl = j >> 7, k = j & 127;
                    xs[bl * 132 + k] = __ldcg(&g_h[wp][l - 1][b0 + bl][k]);
                }
            }
            for (int j = tid; j < 64 * H; j += NT) {
                int bl = j >> 7, k = j & 127;
                hs[bl * 132 + k] = __ldcg(&g_h[rp][l][b0 + bl][k]);
            }
            __syncthreads();

            if (tid < 512) {
                int bl = tid >> 3, ul = (tid >> 1) & 3, ch = tid & 1;
                const ull*   w  = ws + (ul * 2 + ch) * 258;
                const float* xv = xs + bl * 132;
                const float* hv = hs + bl * 132;
                ull acc = 0ull;
#pragma unroll 8
                for (int k = 0; k < 128; k += 2) {
                    float2 x2 = *(const float2*)(xv + k);
                    ulonglong2 w2 = *(const ulonglong2*)(w + k);
                    fma2(acc, pk2(x2.x), w2.x);
                    fma2(acc, pk2(x2.y), w2.y);
                }
#pragma unroll 8
                for (int k = 0; k < 128; k += 2) {
                    float2 h2 = *(const float2*)(hv + k);
                    ulonglong2 w2 = *(const ulonglong2*)(w + 128 + k);
                    fma2(acc, pk2(h2.x), w2.x);
                    fma2(acc, pk2(h2.y), w2.y);
                }
                float2 vv = upk(acc);
                int u = u0 + ul, b = b0 + bl;
                int gA = (ch ? 256 : 0) + u;
                float a0 = vv.x + __ldg(&b_ih[l * 512 + gA])       + __ldg(&b_hh[l * 512 + gA]);
                float a1 = vv.y + __ldg(&b_ih[l * 512 + gA + 128]) + __ldg(&b_hh[l * 512 + gA + 128]);
                float p0 = __shfl_xor_sync(0xffffffffu, a0, 1);
                float p1 = __shfl_xor_sync(0xffffffffu, a1, 1);
                if (ch == 0) {
                    float co = __ldcg(&g_c[rp][l][b][u]);
                    float cn = sigm(a1) * co + sigm(a0) * tanhf(p0);
                    float hn = sigm(p1) * tanhf(cn);
                    __stcg(&g_c[wp][l][b][u], cn);
                    __stcg(&g_h[wp][l][b][u], hn);
                }
            } else if (nzValid) {               // deferred normalize chunk l
                int i0 = l * 1600 + (tid & 255);
                for (int i = i0; i < (l + 1) * 1600; i += 256) {
                    float4 e = __ldcg(nzIn + i);
                    float4 o = { e.x * nzInv, e.y * nzInv, e.z * nzInv, e.w * nzInv };
                    __stcs(nzOut + i, o);
                }
            }
            bumpcnt(&c_hq[l][q][0]);
        }

        // ================= emb: fp32 + bf16 hi/lo split ======================
        {
            waitcnt(&c_hq[NL - 1][q][0], 32 * (t + 1));
            float* hsm = (float*)(smraw + 1024);   // [64][132]
            float* Wts = hsm + 64 * 132;           // [4][128]
            int r0 = q * 64, e0 = ut * 4;
            for (int j = tid; j < 64 * H; j += NT) {
                int row = j >> 7, k = j & 127;
                hsm[row * 132 + k] = __ldcg(&g_h[wp][NL - 1][r0 + row][k]);
            }
            for (int j = tid; j < 4 * H; j += NT)
                Wts[j] = __ldg(&W_re[(e0 + (j >> 7)) * H + (j & 127)]);
            __syncthreads();
            if (tid < 256) {
                int row = tid & 63, e = tid >> 6;
                const float* hv = hsm + row * 132;
                const float* wv = Wts + e * 128;
                float acc = 0.f;
#pragma unroll 8
                for (int k = 0; k < 128; k += 4) {
                    float4 h4 = *(const float4*)(hv + k);
                    float4 w4 = *(const float4*)(wv + k);
                    acc = fmaf(h4.x, w4.x, acc); acc = fmaf(h4.y, w4.y, acc);
                    acc = fmaf(h4.z, w4.z, acc); acc = fmaf(h4.w, w4.w, acc);
                }
                float ev = acc + __ldg(&b_re[e0 + e]);
                __nv_bfloat16 hi = __float2bfloat16(ev);
                int idx = (r0 + row) * H + e0 + e;
                g_ehi[idx] = hi;
                g_elo[idx] = __float2bfloat16(ev - __bfloat162float(hi));
            } else if (tid >= 512 && nzValid) {    // deferred normalize chunk 4
                int i0 = 4 * 1600 + (tid & 255);
                for (int i = i0; i < 8000; i += 256) {
                    float4 e = __ldcg(nzIn + i);
                    float4 o = { e.x * nzInv, e.y * nzInv, e.z * nzInv, e.w * nzInv };
                    __stcs(nzOut + i, o);
                }
            }
            bumpcnt(&c_emb);
        }

        // ================= logits: split-bf16 mma.sync + exp epilogue ========
        waitcnt(&c_emb, NB * (t + 1));     // also guarantees all normalize(t-1) done
        {
            {   // stage A (emb hi/lo)
                const uint4* eh = (const uint4*)g_ehi;
                const uint4* el = (const uint4*)g_elo;
                for (int j = tid; j < 4096; j += NT) {
                    int r = j >> 4, kq = j & 15;
                    *(uint4*)(smraw + SA_HI + r * 272 + kq * 16) = __ldcg(&eh[j]);
                    *(uint4*)(smraw + SA_LO + r * 272 + kq * 16) = __ldcg(&el[j]);
                }
            }
            const int lane = tid & 31, wid = tid >> 5;
            const int m_base = (wid >> 2) * 32;
            const int n_base = (wid & 3) * 32;
            const int arow  = lane & 15;
            const int ahoff = ((lane >> 4) & 1) * 16;
            const int nrow  = (lane & 7) + ((lane & 16) >> 1);
            const int bhoff = ((lane >> 3) & 1) * 16;
            const int qrow = lane >> 2, qcol = (lane & 3) * 2;
            ull*   keys = (ull*)(smraw + SM_KEY);    // [256][4]
            float* sums = (float*)(smraw + SM_SUM);  // [256][4]
            ull gbest = 0ull;
            float rowsum = 0.f;

            for (int u = bid; u < NUNIT; u += NB) {
                int v0 = u * 128;
                {
                    const uint4* wh = (const uint4*)g_Whi;
                    const uint4* wl = (const uint4*)g_Wlo2;
                    int sb = v0 * 16;
                    for (int j = tid; j < 2048; j += NT) {
                        int r = j >> 4, kq = j & 15;
                        *(uint4*)(smraw + SB_HI + r * 272 + kq * 16) = __ldg(&wh[sb + j]);
                        *(uint4*)(smraw + SB_LO + r * 272 + kq * 16) = __ldg(&wl[sb + j]);
                    }
                }
                __syncthreads();

                float c[2][4][4];
#pragma unroll
                for (int mi = 0; mi < 2; mi++)
#pragma unroll
                    for (int n8 = 0; n8 < 4; n8++)
#pragma unroll
                        for (int e = 0; e < 4; e++) c[mi][n8][e] = 0.f;

                unsigned aB = smem_base + SA_HI + (unsigned)(m_base + arow) * 272 + ahoff;
                unsigned bB = smem_base + SB_HI + (unsigned)(n_base + nrow) * 272 + bhoff;
#pragma unroll 1
                for (int ks = 0; ks < 8; ks++) {
                    unsigned koff = ks * 32;
                    unsigned ah[2][4], al[2][4], bb[4][2];
                    ldmx4(ah[0][0], ah[0][1], ah[0][2], ah[0][3], aB + koff);
                    ldmx4(ah[1][0], ah[1][1], ah[1][2], ah[1][3], aB + 16 * 272 + koff);
                    ldmx4(bb[0][0], bb[0][1], bb[1][0], bb[1][1], bB + koff);
                    ldmx4(bb[2][0], bb[2][1], bb[3][0], bb[3][1], bB + 16 * 272 + koff);
#pragma unroll
                    for (int mi = 0; mi < 2; mi++)
#pragma unroll
                        for (int n8 = 0; n8 < 4; n8++)
                            mma_bf16(c[mi][n8], ah[mi], bb[n8]);
                    ldmx4(al[0][0], al[0][1], al[0][2], al[0][3], aB + DLO_A + koff);
                    ldmx4(al[1][0], al[1][1], al[1][2], al[1][3], aB + DLO_A + 16 * 272 + koff);
#pragma unroll
                    for (int mi = 0; mi < 2; mi++)
#pragma unroll
                        for (int n8 = 0; n8 < 4; n8++)
                            mma_bf16(c[mi][n8], al[mi], bb[n8]);
                    ldmx4(bb[0][0], bb[0][1], bb[1][0], bb[1][1], bB + DLO_B + koff);
                    ldmx4(bb[2][0], bb[2][1], bb[3][0], bb[3][1], bB + DLO_B + 16 * 272 + koff);
#pragma unroll
                    for (int mi = 0; mi < 2; mi++)
#pragma unroll
                        for (int n8 = 0; n8 < 4; n8++)
                            mma_bf16(c[mi][n8], ah[mi], bb[n8]);
                }

                // epilogue: shifted bias, per-row keys + partial sums, exp, store e
                ull   bk[2][2] = {{0ull, 0ull}, {0ull, 0ull}};
                float rs[2][2] = {{0.f, 0.f}, {0.f, 0.f}};
#pragma unroll
                for (int mi = 0; mi < 2; mi++) {
                    int r = m_base + mi * 16 + qrow;
#pragma unroll
                    for (int n8 = 0; n8 < 4; n8++) {
                        int v = v0 + n_base + n8 * 8 + qcol;
                        float2 bl = __ldg((const float2*)&g_blo[v]);
                        float o0 = c[mi][n8][0] + bl.x, o1 = c[mi][n8][1] + bl.y;
                        float o2 = c[mi][n8][2] + bl.x, o3 = c[mi][n8][3] + bl.y;
                        bk[mi][0] = max(bk[mi][0], max(mkkey(o0, v), mkkey(o1, v + 1)));
                        bk[mi][1] = max(bk[mi][1], max(mkkey(o2, v), mkkey(o3, v + 1)));
                        float e0x = __expf(o0), e0y = __expf(o1);
                        float e1x = __expf(o2), e1y = __expf(o3);
                        rs[mi][0] += e0x + e0y;
                        rs[mi][1] += e1x + e1y;
                        float2 e0 = { e0x, e0y }, e1 = { e1x, e1y };
                        __stcg((float2*)&g_scr[r][v],     e0);
                        __stcg((float2*)&g_scr[r + 8][v], e1);
                    }
                }
#pragma unroll
                for (int mi = 0; mi < 2; mi++)
#pragma unroll
                    for (int hh = 0; hh < 2; hh++) {
                        ull k = bk[mi][hh];
                        k = max(k, __shfl_xor_sync(0xffffffffu, k, 1));
                        k = max(k, __shfl_xor_sync(0xffffffffu, k, 2));
                        bk[mi][hh] = k;
                        float s = rs[mi][hh];
                        s += __shfl_xor_sync(0xffffffffu, s, 1);
                        s += __shfl_xor_sync(0xffffffffu, s, 2);
                        rs[mi][hh] = s;
                    }
                if ((lane & 3) == 0) {
                    int nw = wid & 3;
#pragma unroll
                    for (int mi = 0; mi < 2; mi++)
#pragma unroll
                        for (int hh = 0; hh < 2; hh++) {
                            int row = m_base + mi * 16 + qrow + hh * 8;
                            keys[row * 4 + nw] = bk[mi][hh];
                            sums[row * 4 + nw] = rs[mi][hh];
                        }
                }
                __syncthreads();
                if (tid < 256) {
                    gbest = max(gbest, max(max(keys[tid * 4], keys[tid * 4 + 1]),
                                           max(keys[tid * 4 + 2], keys[tid * 4 + 3])));
                    rowsum += (sums[tid * 4] + sums[tid * 4 + 1])
                            + (sums[tid * 4 + 2] + sums[tid * 4 + 3]);
                }
            }
            if (tid < 256) {
                if (gbest != 0ull) atomicMax(&g_amax[rp][tid], gbest);
                __stcg(&g_psum[tid][bid], rowsum);
            }
        }
        bumpcnt(&c_log);

        // ====== softmax head: tiny deterministic reduce + feedback ===========
        waitcnt(&c_log, NB * (t + 1));
        {
            float* sInv = (float*)(smraw + 1024);  // [2]
            int half = tid >> 9;
            int r = 2 * bid + half;
            if ((tid & 511) < 32) {                // one warp per row
                int L = tid & 31;
                float s = 0.f;
                for (int j = L; j < NB; j += 32) s += __ldcg(&g_psum[r][j]);
#pragma unroll
                for (int off = 16; off; off >>= 1)
                    s += __shfl_xor_sync(0xffffffffu, s, off);
                if (L == 0) {
                    sInv[half] = 1.f / s;
                    ull key = *(volatile ull*)&g_amax[rp][r];
                    __stcg(&g_prev[r], (int)(0xffffffffu - (unsigned)(key & 0xffffffffu)));
                    atomicExch(&g_amax[rp][r], 0ull);
                }
            }
            __syncthreads();
            if (t < TSTEP - 1) {
                if (tid >= 512) {                  // arm deferred normalize
                    int rn = 2 * bid + ((tid >> 8) & 1);
                    nzIn  = (const float4*)&g_scr[rn][0];
                    nzOut = (float4*)(out + ((size_t)t * BATCH + rn) * V);
                    nzInv = sInv[(tid >> 8) & 1];
                    nzValid = 1;
                }
                bumpcnt(&c_redq[bid >> 5][0]);     // release step t+1 LSTM now
            } else {                               // last step: inline normalize
                bumpcnt(&c_redq[bid >> 5][0]);
                float invv = sInv[half];
                const float4* row4 = (const float4*)&g_scr[r][0];
                float4* orow = (float4*)(out + ((size_t)t * BATCH + r) * V);
                for (int i = tid & 511; i < V / 4; i += 512) {
                    float4 e = __ldcg(&row4[i]);
                    float4 o = { e.x * invv, e.y * invv, e.z * invv, e.w * invv };
                    __stcs(&orow[i], o);
                }
            }
        }
    }

    // ---- reset counters for graph replay ----
    __syncthreads();
    if (tid == 0) {
        __threadfence();
        atomicAdd(&c_done, 1);
        if (bid == 0) {
            volatile int* vd = (volatile int*)&c_done;
            while (*vd < NB) __nanosleep(64);
            c_init = 0; c_emb = 0; c_log = 0;
            g_mw2key = 0; g_mbkey = 0;
            for (int l = 0; l < NL; l++)
                for (int qq = 0; qq < 4; qq++) c_hq[l][qq][0] = 0;
            for (int qq = 0; qq < 4; qq++) c_redq[qq][0] = 0;
            __threadfence();
            *(volatile int*)&c_done = 0;
        }
    }
}

// ---------------- launch ----------------
extern "C" void kernel_launch(void* const* d_in, const int* in_sizes, int n_in,
                              void* d_out, int out_size) {
    const float* hidden = (const float*)d_in[0];
    const float* cell   = (const float*)d_in[1];
    const float* W_in   = (const float*)d_in[2];
    const float* b_in   = (const float*)d_in[3];
    const float* W_ih   = (const float*)d_in[4];
    const float* W_hh   = (const float*)d_in[5];
    const float* b_ih   = (const float*)d_in[6];
    const float* b_hh   = (const float*)d_in[7];
    const float* W_re   = (const float*)d_in[8];
    const float* b_re   = (const float*)d_in[9];
    const float* W_lo   = (const float*)d_in[10];
    const float* b_lo   = (const float*)d_in[11];
    const int*   eos    = (const int*)d_in[12];
    float* out = (float*)d_out;

    cudaFuncSetAttribute(decoder_kernel, cudaFuncAttributeMaxDynamicSharedMemorySize, SMEM_BYTES);
    decoder_kernel<<<NB, NT, SMEM_BYTES>>>(hidden, cell, W_in, b_in, W_ih, W_hh,
                                           b_ih, b_hh, W_re, b_re, W_lo, b_lo, eos, out);
}